// round 4
// baseline (speedup 1.0000x reference)
#include <cuda_runtime.h>
#include <math.h>
#include <stdint.h>

#define Bn 8192
#define Tn 5
#define Fn 923
#define Hn 64
#define Gn 256
#define EPSc 1e-5f

typedef unsigned long long ull;

// ---------------- scratch layout ----------------
constexpr size_t AL(size_t x) { return (x + 15) & ~(size_t)15; }

constexpr size_t O_H      = 0;
constexpr size_t O_C      = AL(O_H + (size_t)Bn * Hn);
constexpr size_t O_YH     = AL(O_C + (size_t)Bn * Hn);
constexpr size_t O_ACC    = AL(O_YH + (size_t)Bn * 2);
constexpr size_t O_XCAT   = AL(O_ACC + 32);                       // [B, 992]
constexpr size_t O_GATES  = AL(O_XCAT + (size_t)Bn * 992);        // [B, 256]
constexpr size_t O_ENC    = AL(O_GATES + (size_t)Bn * Gn);        // [B,T,923]
constexpr size_t O_ENCPG  = AL(O_ENC + (size_t)Bn * Tn * Fn);     // [B,T,320]
constexpr size_t O_TDPRE  = AL(O_ENCPG + (size_t)Bn * Tn * 320);  // [B,T,64]
constexpr size_t O_MASKG  = AL(O_TDPRE + (size_t)Bn * Tn * Hn);   // [B,T,256]
constexpr size_t O_WHE    = AL(O_MASKG + (size_t)Bn * Tn * Gn);   // [64,1846]
constexpr size_t O_BHE    = AL(O_WHE + (size_t)Hn * 2 * Fn);      // [1846]
constexpr size_t O_WCOMB  = AL(O_BHE + 2 * Fn);                   // [987,256]
constexpr size_t O_MASKW  = AL(O_WCOMB + (size_t)987 * Gn);       // [923,256]
constexpr size_t O_TDWT   = AL(O_MASKW + (size_t)Fn * Gn);        // [923,64]
constexpr size_t O_WENC2  = AL(O_TDWT + (size_t)Fn * Hn);         // [923,320]
constexpr size_t O_B2     = AL(O_WENC2 + (size_t)Fn * 320);       // [320]
constexpr size_t O_ATTWHT = AL(O_B2 + 320);                       // [64,64]
constexpr size_t O_DWHHT  = AL(O_ATTWHT + Hn * Hn);               // [64,256]
constexpr size_t TOTAL_FLOATS = AL(O_DWHHT + (size_t)Hn * Gn) + 16;

static __device__ float g_buf[TOTAL_FLOATS];

// ---------------- helpers ----------------
__device__ __forceinline__ float sigmoidf_(float x) { return 1.0f / (1.0f + expf(-x)); }
__device__ __forceinline__ float rnd6(float v) { return rintf(v * 1e6f) / 1e6f; }

__device__ __forceinline__ void upk2(ull v, float& lo, float& hi) {
    asm("mov.b64 {%0, %1}, %2;" : "=f"(lo), "=f"(hi) : "l"(v));
}
__device__ __forceinline__ void fma2(ull& d, ull a, ull b) {
    asm("fma.rn.f32x2 %0, %1, %2, %0;" : "+l"(d) : "l"(a), "l"(b));
}

// reduce 2 values across block into atomics; buf = >=64 floats shared scratch
__device__ __forceinline__ void red2(float v0, float v1, float* buf, float* a0, float* a1) {
    int lane = threadIdx.x & 31, w = threadIdx.x >> 5;
#pragma unroll
    for (int o = 16; o; o >>= 1) {
        v0 += __shfl_down_sync(0xffffffffu, v0, o);
        v1 += __shfl_down_sync(0xffffffffu, v1, o);
    }
    if (lane == 0) { buf[w] = v0; buf[32 + w] = v1; }
    __syncthreads();
    if (w == 0) {
        int nw = (blockDim.x + 31) >> 5;
        v0 = (lane < nw) ? buf[lane] : 0.0f;
        v1 = (lane < nw) ? buf[32 + lane] : 0.0f;
#pragma unroll
        for (int o = 16; o; o >>= 1) {
            v0 += __shfl_down_sync(0xffffffffu, v0, o);
            v1 += __shfl_down_sync(0xffffffffu, v1, o);
        }
        if (lane == 0) { atomicAdd(a0, v0); atomicAdd(a1, v1); }
    }
}

// ---------------- pack / init kernels ----------------
__global__ void k_zero(float* p, int n) {
    int i = blockIdx.x * blockDim.x + threadIdx.x;
    if (i < n) p[i] = 0.0f;
}
__global__ void k_zerocols(float* xcat) {
    int i = blockIdx.x * blockDim.x + threadIdx.x;
    if (i < Bn * 69) { int b = i / 69, j = i % 69; xcat[(size_t)b * 992 + 923 + j] = 0.0f; }
}
__global__ void k_pack_whe(const float* __restrict__ histW, const float* __restrict__ encW,
                           const float* __restrict__ histb, const float* __restrict__ encb,
                           float* __restrict__ dst, float* __restrict__ bias) {
    int i = blockIdx.x * blockDim.x + threadIdx.x;
    if (i < Hn * 2 * Fn) {
        int k = i / (2 * Fn), n = i % (2 * Fn);
        dst[i] = (n < Fn) ? histW[n * Hn + k] : encW[(n - Fn) * Hn + k];
    }
    if (i < 2 * Fn) bias[i] = (i < Fn) ? histb[i] : encb[i - Fn];
}
__global__ void k_pack_wcomb(const float* __restrict__ Wih, const float* __restrict__ Whh,
                             float* __restrict__ dst) {
    int i = blockIdx.x * blockDim.x + threadIdx.x;
    if (i < 987 * Gn) {
        int k = i / Gn, j = i % Gn;
        dst[i] = (k < Fn) ? Wih[j * (2 * Fn) + k] : Whh[j * Hn + (k - Fn)];
    }
}
__global__ void k_pack_maskW(const float* __restrict__ Wih, float* __restrict__ dst) {
    int i = blockIdx.x * blockDim.x + threadIdx.x;
    if (i < Fn * Gn) { int k = i / Gn, j = i % Gn; dst[i] = Wih[j * (2 * Fn) + Fn + k]; }
}
__global__ void k_pack_wenc2(const float* __restrict__ attW, const float* __restrict__ decWih,
                             const float* __restrict__ attb, const float* __restrict__ decb,
                             float* __restrict__ dst, float* __restrict__ bias) {
    int i = blockIdx.x * blockDim.x + threadIdx.x;
    if (i < Fn * 320) {
        int k = i / 320, n = i % 320;
        dst[i] = (n < Hn) ? attW[n * 987 + Hn + k] : decWih[(n - Hn) * 925 + 2 + k];
    }
    if (i < 320) bias[i] = (i < Hn) ? attb[i] : decb[i - Hn];
}
__global__ void k_pack_misc(const float* __restrict__ attW, const float* __restrict__ decWhh,
                            const float* __restrict__ tdW, float* __restrict__ attWhT,
                            float* __restrict__ dWhhT, float* __restrict__ tdWt,
                            float* __restrict__ acc) {
    int i = blockIdx.x * blockDim.x + threadIdx.x;
    if (i < 32) acc[i] = 0.0f;
    if (i < Hn * Hn) { int k = i / Hn, j = i % Hn; attWhT[i] = attW[j * 987 + k]; }
    if (i < Hn * Gn) { int k = i / Gn, j = i % Gn; dWhhT[i] = decWhh[j * Hn + k]; }
    if (i < Fn * Hn) { int k = i / Hn, j = i % Hn; tdWt[i] = tdW[j * Fn + k]; }
}

// ---------------- SGEMM: FFMA2, dup-A smem, pair-N accumulators ----------------
// block 256 threads (16x16), BM = TM*16, BN = NPAIRS*32, thread tile TM x (2*NPAIRS).
// EPI 0: C = acc + bias ; EPI 1: C = acc + add[m*addLd+n] ; EPI 2: histenc fused epilogue.
template<int TM, int NPAIRS, int EPI>
__global__ __launch_bounds__(256) void sgemm(
    const float* __restrict__ A, int lda,
    const float* __restrict__ Bt, int ldb,
    float* __restrict__ C, int ldc,
    const float* __restrict__ bias,
    const float* __restrict__ add, int addLd,
    int N, int K,
    const float* __restrict__ values, const float* __restrict__ masks,
    float* __restrict__ outImp, float* __restrict__ xcat,
    float* __restrict__ enc, float* __restrict__ accp, int t)
{
    constexpr int BM = TM * 16;
    constexpr int BN = NPAIRS * 32;
    constexpr int TPR = 16 / TM;      // threads cooperating on one A row (k-split)
    constexpr int BL = BN / 16;       // B elems per thread per tile

    __shared__ __align__(16) float As[2][16][BM * 2];  // dup pairs along M
    __shared__ __align__(16) float Bs[2][16][BN];

    const int tid = threadIdx.x;
    const int tx = tid & 15, ty = tid >> 4;
    const int m0 = blockIdx.y * BM, n0 = blockIdx.x * BN;
    const int ar = tid / TPR;                 // A row within tile
    const int ak = (tid % TPR) * TM;          // A k-offset (TM consecutive k)
    const int bk = tid >> 4, bn = tid & 15;   // B: row k, col base (stride 16)

    float Ar[TM], Br[BL];

    auto loadA = [&](int k0) {
        const float* ap = A + (size_t)(m0 + ar) * lda + k0 + ak;
#pragma unroll
        for (int i = 0; i < TM; i++) {
            int k = k0 + ak + i;
            Ar[i] = (k < K) ? ap[i] : 0.0f;
        }
    };
    auto loadB = [&](int k0) {
        int k = k0 + bk;
        const float* bp = Bt + (size_t)k * ldb + n0 + bn;
        bool kv = (k < K);
#pragma unroll
        for (int i = 0; i < BL; i++) {
            int n = n0 + bn + 16 * i;
            Br[i] = (kv && n < N) ? bp[16 * i] : 0.0f;
        }
    };
    auto storeA = [&](int buf) {
#pragma unroll
        for (int i = 0; i < TM; i++)
            *(float2*)&As[buf][ak + i][ar * 2] = make_float2(Ar[i], Ar[i]);
    };
    auto storeB = [&](int buf) {
#pragma unroll
        for (int i = 0; i < BL; i++) Bs[buf][bk][bn + 16 * i] = Br[i];
    };

    loadA(0); loadB(0); storeA(0); storeB(0);
    __syncthreads();

    ull acc[TM][NPAIRS];
#pragma unroll
    for (int i = 0; i < TM; i++)
#pragma unroll
        for (int j = 0; j < NPAIRS; j++) acc[i][j] = 0ULL;

    const int NT = (K + 15) >> 4;
    int cur = 0;
    for (int t0 = 0; t0 < NT; t0++) {
        const bool pf = (t0 + 1 < NT);
        if (pf) { loadA((t0 + 1) << 4); loadB((t0 + 1) << 4); }
#pragma unroll
        for (int kk = 0; kk < 16; kk++) {
            ull a2[TM];
#pragma unroll
            for (int i = 0; i < TM / 2; i++) {
                ulonglong2 v = *(const ulonglong2*)&As[cur][kk][ty * TM * 2 + i * 4];
                a2[2 * i] = v.x; a2[2 * i + 1] = v.y;
            }
            ull b2[NPAIRS];
#pragma unroll
            for (int j = 0; j < NPAIRS; j++)
                b2[j] = *(const ull*)&Bs[cur][kk][2 * tx + 32 * j];
#pragma unroll
            for (int i = 0; i < TM; i++)
#pragma unroll
                for (int j = 0; j < NPAIRS; j++) fma2(acc[i][j], a2[i], b2[j]);
        }
        if (pf) { storeA(cur ^ 1); storeB(cur ^ 1); }
        __syncthreads();
        cur ^= 1;
    }

    // ---- epilogue ----
    float ds = 0.0f, ms = 0.0f;
#pragma unroll
    for (int i = 0; i < TM; i++) {
        int m = m0 + ty * TM + i;
#pragma unroll
        for (int j = 0; j < NPAIRS; j++) {
            float lo, hi; upk2(acc[i][j], lo, hi);
#pragma unroll
            for (int h = 0; h < 2; h++) {
                float v = h ? hi : lo;
                int n = n0 + 2 * tx + 32 * j + h;
                if (n < N) {
                    if (EPI == 0) {
                        C[(size_t)m * ldc + n] = v + bias[n];
                    } else if (EPI == 1) {
                        C[(size_t)m * ldc + n] = v + add[(size_t)m * addLd + n];
                    } else {
                        v += bias[n];
                        if (n < Fn) {
                            size_t gi = ((size_t)m * Tn + t) * Fn + n;
                            float x = values[gi], mm = masks[gi];
                            float d = (x - v) * mm;
                            ds += d * d; ms += mm;
                            float xcv = fmaf(mm, x - v, v);
                            xcat[(size_t)m * 992 + n] = xcv;
                            outImp[gi] = rnd6(xcv);
                        } else {
                            int f = n - Fn;
                            size_t gi = ((size_t)m * Tn + t) * Fn + f;
                            enc[gi] = tanhf(v) * masks[gi];
                        }
                    }
                }
            }
        }
    }
    if (EPI == 2) red2(ds, ms, &As[0][0][0], accp + 2 * t, accp + 2 * t + 1);
}

// ---------------- LSTM pointwise (encoder) ----------------
__global__ void k_lstm(const float* __restrict__ gates, float* __restrict__ h, float* __restrict__ c,
                       float* __restrict__ xcat, const float* __restrict__ tdPre, int t)
{
    int i = blockIdx.x * blockDim.x + threadIdx.x;
    if (i >= Bn * Hn) return;
    int b = i >> 6, j = i & 63;
    const float* g = gates + (size_t)b * Gn;
    float cv = sigmoidf_(g[64 + j]) * c[i] + sigmoidf_(g[j]) * tanhf(g[128 + j]);
    float hv = sigmoidf_(g[192 + j]) * tanhf(cv);
    c[i] = cv;
    if (t < Tn - 1) {
        float gm = expf(-fmaxf(tdPre[((size_t)b * Tn + t + 1) * Hn + j], 0.0f));
        hv *= gm;
        xcat[(size_t)b * 992 + Fn + j] = hv;
    }
    h[i] = hv;
}

__global__ void k_yh0(const float* __restrict__ pH, const float* __restrict__ outW,
                      const float* __restrict__ outb, const float* __restrict__ labels,
                      const float* __restrict__ masky, float* __restrict__ pYH,
                      float* __restrict__ outDec, float* __restrict__ accp)
{
    __shared__ float buf[64];
    int gid = blockIdx.x * blockDim.x + threadIdx.x;
    int b = gid >> 1, o = gid & 1;
    const float* hr = pH + (size_t)b * Hn;
    const float* wr = outW + o * Hn;
    float s = outb[o];
#pragma unroll
    for (int k = 0; k < Hn; k++) s += hr[k] * wr[k];
    pYH[gid] = s;
    size_t li = ((size_t)b * Tn + (Tn - 1)) * 2 + o;
    float l0 = labels[li], m0 = masky[li];
    float d = (s - l0) * m0;
    outDec[li] = rnd6(l0 * m0 + s * (1.0f - m0));
    red2(d * d, m0, buf, accp + 10, accp + 11);
}

// ---------------- fused decoder step ----------------
__global__ __launch_bounds__(256) void k_decstep(
    const float* __restrict__ labels, const float* __restrict__ masky,
    float* __restrict__ pH, float* __restrict__ pC, float* __restrict__ pYH,
    const float* __restrict__ encPG, const float* __restrict__ attWhT,
    const float* __restrict__ dWhhT, const float* __restrict__ decWih,
    const float* __restrict__ attv, const float* __restrict__ outW,
    const float* __restrict__ outb, float* __restrict__ outDec,
    float* __restrict__ accp, int td)
{
    int b = blockIdx.x, tid = threadIdx.x;
    __shared__ float sh[64], shp[64], siy[2], se[5], sattn[5], sg[256], shn[64], syh[2];
    __shared__ float rbuf[64];
    const int tr = Tn - 1 - td;

    if (tid < 64) sh[tid] = pH[(size_t)b * Hn + tid];
    if (tid >= 64 && tid < 66) {
        int o = tid - 64;
        size_t li = ((size_t)b * Tn + tr) * 2 + o;
        float lv = labels[li], mv = masky[li];
        float v = lv * mv + pYH[b * 2 + o] * (1.0f - mv);
        siy[o] = v;
        outDec[li] = rnd6(v);
    }
    __syncthreads();

    if (tid < 64) {
        float s = 0.0f;
#pragma unroll 16
        for (int k = 0; k < 64; k++) s += sh[k] * attWhT[k * 64 + tid];
        shp[tid] = s;
    }
    __syncthreads();

    int w = tid >> 5, lane = tid & 31;
    if (w < Tn) {
        const float* ep = encPG + ((size_t)b * Tn + w) * 320;
        float p = attv[lane] * tanhf(shp[lane] + ep[lane])
                + attv[lane + 32] * tanhf(shp[lane + 32] + ep[lane + 32]);
#pragma unroll
        for (int o = 16; o; o >>= 1) p += __shfl_down_sync(0xffffffffu, p, o);
        if (lane == 0) se[w] = p;
    }
    __syncthreads();
    if (tid == 0) {
        float mx = se[0];
#pragma unroll
        for (int k = 1; k < Tn; k++) mx = fmaxf(mx, se[k]);
        float sum = 0.0f;
#pragma unroll
        for (int k = 0; k < Tn; k++) { sattn[k] = expf(se[k] - mx); sum += sattn[k]; }
        float inv = 1.0f / sum;
#pragma unroll
        for (int k = 0; k < Tn; k++) sattn[k] *= inv;
    }
    __syncthreads();

    {
        const float* eg = encPG + (size_t)b * Tn * 320 + 64;
        float g = sattn[0] * eg[tid] + sattn[1] * eg[320 + tid] + sattn[2] * eg[640 + tid]
                + sattn[3] * eg[960 + tid] + sattn[4] * eg[1280 + tid];
#pragma unroll 16
        for (int k = 0; k < 64; k++) g += sh[k] * dWhhT[k * 256 + tid];
        g += siy[0] * decWih[tid * 925 + 0] + siy[1] * decWih[tid * 925 + 1];
        sg[tid] = g;
    }
    __syncthreads();

    if (tid < 64) {
        float cv = sigmoidf_(sg[64 + tid]) * pC[(size_t)b * Hn + tid]
                 + sigmoidf_(sg[tid]) * tanhf(sg[128 + tid]);
        float hv = sigmoidf_(sg[192 + tid]) * tanhf(cv);
        pC[(size_t)b * Hn + tid] = cv;
        pH[(size_t)b * Hn + tid] = hv;
        shn[tid] = hv;
    }
    __syncthreads();

    if (w < 2) {
        float p = shn[lane] * outW[w * 64 + lane] + shn[lane + 32] * outW[w * 64 + lane + 32];
#pragma unroll
        for (int o = 16; o; o >>= 1) p += __shfl_down_sync(0xffffffffu, p, o);
        if (lane == 0) { float yv = p + outb[w]; syh[w] = yv; pYH[b * 2 + w] = yv; }
    }
    __syncthreads();

    float ds = 0.0f, ms = 0.0f;
    if (tid < 2) {
        size_t li = ((size_t)b * Tn + tr) * 2 + tid;
        float d = (syh[tid] - labels[li]) * masky[li];
        ds = d * d; ms = masky[li];
    }
    red2(ds, ms, rbuf, accp + 10 + 2 * td, accp + 11 + 2 * td);
}

__global__ void k_final(const float* __restrict__ acc, float* __restrict__ out) {
    if (threadIdx.x == 0) {
        float xl = 0.0f, yl = 0.0f;
#pragma unroll
        for (int t = 0; t < Tn; t++)
            xl += (acc[2 * t] / ((float)Bn * (float)Fn)) / (acc[2 * t + 1] + EPSc);
#pragma unroll
        for (int td = 0; td < Tn; td++)
            yl += (acc[10 + 2 * td] / ((float)Bn * 2.0f)) / (acc[11 + 2 * td] + EPSc);
        out[0] = xl / (float)Tn + yl / (float)Tn;
    }
}

// ---------------- host orchestration ----------------
extern "C" void kernel_launch(void* const* d_in, const int* in_sizes, int n_in,
                              void* d_out, int out_size)
{
    const float* values  = (const float*)d_in[0];
    const float* masks   = (const float*)d_in[1];
    const float* deltas  = (const float*)d_in[2];
    const float* labels  = (const float*)d_in[3];
    const float* masks_y = (const float*)d_in[4];
    const float* td_W    = (const float*)d_in[5];
    const float* td_b    = (const float*)d_in[6];
    const float* hist_W  = (const float*)d_in[7];
    const float* hist_b  = (const float*)d_in[8];
    const float* enc_W   = (const float*)d_in[9];
    const float* enc_b   = (const float*)d_in[10];
    const float* rnn_Wih = (const float*)d_in[11];
    const float* rnn_Whh = (const float*)d_in[12];
    const float* rnn_b   = (const float*)d_in[13];
    const float* dec_Wih = (const float*)d_in[14];
    const float* dec_Whh = (const float*)d_in[15];
    const float* dec_b   = (const float*)d_in[16];
    const float* att_W   = (const float*)d_in[17];
    const float* att_b   = (const float*)d_in[18];
    const float* att_v   = (const float*)d_in[19];
    const float* out_W   = (const float*)d_in[20];
    const float* out_b   = (const float*)d_in[21];

    float* out = (float*)d_out;
    float* outImp = out + 1;
    float* outDec = out + 1 + (size_t)Bn * Tn * Fn;

    float* gb = nullptr;
    cudaGetSymbolAddress((void**)&gb, g_buf);

    float* pH     = gb + O_H;
    float* pC     = gb + O_C;
    float* pYH    = gb + O_YH;
    float* pAcc   = gb + O_ACC;
    float* pXCAT  = gb + O_XCAT;
    float* pGATES = gb + O_GATES;
    float* pENC   = gb + O_ENC;
    float* pENCPG = gb + O_ENCPG;
    float* pTDPRE = gb + O_TDPRE;
    float* pMASKG = gb + O_MASKG;
    float* pWHE   = gb + O_WHE;
    float* pBHE   = gb + O_BHE;
    float* pWCOMB = gb + O_WCOMB;
    float* pMASKW = gb + O_MASKW;
    float* pTDWT  = gb + O_TDWT;
    float* pWENC2 = gb + O_WENC2;
    float* pB2    = gb + O_B2;
    float* pATTWHT= gb + O_ATTWHT;
    float* pDWHHT = gb + O_DWHHT;

    const float* NUL = nullptr;

    // ---- packs (launches 1-5) ----
    k_pack_whe  <<<(Hn * 2 * Fn + 255) / 256, 256>>>(hist_W, enc_W, hist_b, enc_b, pWHE, pBHE);
    k_pack_wcomb<<<(987 * Gn + 255) / 256, 256>>>(rnn_Wih, rnn_Whh, pWCOMB);
    k_pack_maskW<<<(Fn * Gn + 255) / 256, 256>>>(rnn_Wih, pMASKW);
    k_pack_wenc2<<<(Fn * 320 + 255) / 256, 256>>>(att_W, dec_Wih, att_b, dec_b, pWENC2, pB2);
    k_pack_misc <<<(Fn * Hn + 255) / 256, 256>>>(att_W, dec_Whh, td_W, pATTWHT, pDWHHT, pTDWT, pAcc);

    // ---- launch #6 (ncu target): maskG = masks @ maskW + rnn_b ; [40960,256] K=923 ----
    {
        dim3 g(2, 320);
        sgemm<8, 4, 0><<<g, 256>>>(masks, Fn, pMASKW, Gn, pMASKG, Gn, rnn_b,
                                   NUL, 0, Gn, Fn, NUL, NUL, nullptr, nullptr, nullptr, nullptr, 0);
    }
    // tdPre = deltas @ tdWt + td_b ; [40960,64] K=923
    {
        dim3 g(1, 320);
        sgemm<8, 2, 0><<<g, 256>>>(deltas, Fn, pTDWT, Hn, pTDPRE, Hn, td_b,
                                   NUL, 0, Hn, Fn, NUL, NUL, nullptr, nullptr, nullptr, nullptr, 0);
    }

    k_zero<<<(2 * Bn * Hn + 255) / 256, 256>>>(pH, 2 * Bn * Hn);
    k_zerocols<<<(Bn * 69 + 255) / 256, 256>>>(pXCAT);

    // ---- encoder ----
    for (int t = 0; t < Tn; t++) {
        // hist+enc fused: [8192,1846] = h[8192,64] @ WHE ; K=64
        {
            dim3 g((2 * Fn + 127) / 128, Bn / 128);
            sgemm<8, 4, 2><<<g, 256>>>(pH, Hn, pWHE, 2 * Fn, nullptr, 0, pBHE,
                                       NUL, 0, 2 * Fn, Hn,
                                       values, masks, outImp, pXCAT, pENC, pAcc, t);
        }
        // gates: [8192,256] = xcat[8192,992(987)] @ WCOMB + maskG[:,t,:]
        {
            dim3 g(2, Bn / 64);
            sgemm<4, 4, 1><<<g, 256>>>(pXCAT, 992, pWCOMB, Gn, pGATES, Gn, NUL,
                                       pMASKG + (size_t)t * Gn, Tn * Gn, Gn, 987,
                                       NUL, NUL, nullptr, nullptr, nullptr, nullptr, 0);
        }
        k_lstm<<<(Bn * Hn + 255) / 256, 256>>>(pGATES, pH, pC, pXCAT, pTDPRE, t);
    }

    // ---- y_h + first decoder output ----
    k_yh0<<<Bn * 2 / 128, 128>>>(pH, out_W, out_b, labels, masks_y, pYH, outDec, pAcc);

    // encPG = enc @ WENC2 + B2 ; [40960,320] K=923
    {
        dim3 g(3, 320);
        sgemm<8, 4, 0><<<g, 256>>>(pENC, Fn, pWENC2, 320, pENCPG, 320, pB2,
                                   NUL, 0, 320, Fn, NUL, NUL, nullptr, nullptr, nullptr, nullptr, 0);
    }

    // ---- decoder ----
    for (int td = 1; td < Tn; td++) {
        k_decstep<<<Bn, 256>>>(labels, masks_y, pH, pC, pYH, pENCPG, pATTWHT,
                               pDWHHT, dec_Wih, att_v, out_W, out_b, outDec, pAcc, td);
    }

    k_final<<<1, 32>>>(pAcc, out);
}

// round 6
// speedup vs baseline: 1.6462x; 1.6462x over previous
#include <cuda_runtime.h>
#include <math.h>
#include <stdint.h>

#define Bn 8192
#define Tn 5
#define Fn 923
#define Hn 64
#define Gn 256
#define EPSc 1e-5f

// ---------------- scratch layout ----------------
constexpr size_t AL(size_t x) { return (x + 15) & ~(size_t)15; }

constexpr size_t O_H      = 0;
constexpr size_t O_C      = AL(O_H + (size_t)Bn * Hn);
constexpr size_t O_YH     = AL(O_C + (size_t)Bn * Hn);
constexpr size_t O_ACC    = AL(O_YH + (size_t)Bn * 2);
constexpr size_t O_XCAT   = AL(O_ACC + 32);                       // [B, 992]
constexpr size_t O_GATES  = AL(O_XCAT + (size_t)Bn * 992);        // [B, 256]
constexpr size_t O_ENC    = AL(O_GATES + (size_t)Bn * Gn);        // [B,T,923]
constexpr size_t O_ENCPG  = AL(O_ENC + (size_t)Bn * Tn * Fn);     // [B,T,320]
constexpr size_t O_TDPRE  = AL(O_ENCPG + (size_t)Bn * Tn * 320);  // [B,T,64]
constexpr size_t O_MASKG  = AL(O_TDPRE + (size_t)Bn * Tn * Hn);   // [B,T,256]
constexpr size_t O_WHE2   = AL(O_MASKG + (size_t)Bn * Tn * Gn);   // [1846,64]
constexpr size_t O_BHE    = AL(O_WHE2 + (size_t)2 * Fn * Hn);     // [1846]
constexpr size_t O_WCOMB2 = AL(O_BHE + 2 * Fn);                   // [256,987]
constexpr size_t O_WENC2B = AL(O_WCOMB2 + (size_t)Gn * 987);      // [320,923]
constexpr size_t O_B2     = AL(O_WENC2B + (size_t)320 * Fn);      // [320]
constexpr size_t O_ATTWHT = AL(O_B2 + 320);                       // [64,64]
constexpr size_t O_DWHHT  = AL(O_ATTWHT + Hn * Hn);               // [64,256]
constexpr size_t TOTAL_FLOATS = AL(O_DWHHT + (size_t)Hn * Gn) + 16;

static __device__ float g_buf[TOTAL_FLOATS];

// ---------------- helpers ----------------
__device__ __forceinline__ float sigmoidf_(float x) { return 1.0f / (1.0f + expf(-x)); }
__device__ __forceinline__ float rnd6(float v) { return rintf(v * 1e6f) / 1e6f; }
__device__ __forceinline__ uint32_t f2tf32(float v) {
    uint32_t r; asm("cvt.rna.tf32.f32 %0, %1;" : "=r"(r) : "f"(v)); return r;
}
__device__ __forceinline__ void mma_tf32(float* d, const uint32_t* a, const uint32_t* b) {
    asm volatile(
        "mma.sync.aligned.m16n8k8.row.col.f32.tf32.tf32.f32 "
        "{%0,%1,%2,%3}, {%4,%5,%6,%7}, {%8,%9}, {%0,%1,%2,%3};"
        : "+f"(d[0]), "+f"(d[1]), "+f"(d[2]), "+f"(d[3])
        : "r"(a[0]), "r"(a[1]), "r"(a[2]), "r"(a[3]), "r"(b[0]), "r"(b[1]));
}

__device__ __forceinline__ void red2(float v0, float v1, float* buf, float* a0, float* a1) {
    int lane = threadIdx.x & 31, w = threadIdx.x >> 5;
#pragma unroll
    for (int o = 16; o; o >>= 1) {
        v0 += __shfl_down_sync(0xffffffffu, v0, o);
        v1 += __shfl_down_sync(0xffffffffu, v1, o);
    }
    if (lane == 0) { buf[w] = v0; buf[32 + w] = v1; }
    __syncthreads();
    if (w == 0) {
        int nw = (blockDim.x + 31) >> 5;
        v0 = (lane < nw) ? buf[lane] : 0.0f;
        v1 = (lane < nw) ? buf[32 + lane] : 0.0f;
#pragma unroll
        for (int o = 16; o; o >>= 1) {
            v0 += __shfl_down_sync(0xffffffffu, v0, o);
            v1 += __shfl_down_sync(0xffffffffu, v1, o);
        }
        if (lane == 0) { atomicAdd(a0, v0); atomicAdd(a1, v1); }
    }
}

// ---------------- pack kernels ----------------
__global__ void k_zero(float* p, int n) {
    int i = blockIdx.x * blockDim.x + threadIdx.x;
    if (i < n) p[i] = 0.0f;
}
// zero xcat cols 923..991 — REQUIRED each call: t=0 gates GEMM reads h-cols as zero
__global__ void k_zerocols(float* xcat) {
    int i = blockIdx.x * blockDim.x + threadIdx.x;
    if (i < Bn * 69) { int b = i / 69, j = i % 69; xcat[(size_t)b * 992 + 923 + j] = 0.0f; }
}
// WHE2 [1846][64]
__global__ void k_pack_whe2(const float* __restrict__ histW, const float* __restrict__ encW,
                            const float* __restrict__ histb, const float* __restrict__ encb,
                            float* __restrict__ dst, float* __restrict__ bias) {
    int i = blockIdx.x * blockDim.x + threadIdx.x;
    if (i < 2 * Fn * Hn) dst[i] = (i < Fn * Hn) ? histW[i] : encW[i - Fn * Hn];
    if (i < 2 * Fn) bias[i] = (i < Fn) ? histb[i] : encb[i - Fn];
}
// WCOMB2 [256][987]
__global__ void k_pack_wcomb2(const float* __restrict__ Wih, const float* __restrict__ Whh,
                              float* __restrict__ dst) {
    int i = blockIdx.x * blockDim.x + threadIdx.x;
    if (i < Gn * 987) {
        int n = i / 987, k = i % 987;
        dst[i] = (k < Fn) ? Wih[(size_t)n * (2 * Fn) + k] : Whh[n * Hn + (k - Fn)];
    }
}
// WENC2B [320][923]
__global__ void k_pack_wenc2b(const float* __restrict__ attW, const float* __restrict__ decWih,
                              const float* __restrict__ attb, const float* __restrict__ decb,
                              float* __restrict__ dst, float* __restrict__ bias) {
    int i = blockIdx.x * blockDim.x + threadIdx.x;
    if (i < 320 * Fn) {
        int n = i / Fn, k = i % Fn;
        dst[i] = (n < Hn) ? attW[n * 987 + Hn + k] : decWih[(size_t)(n - Hn) * 925 + 2 + k];
    }
    if (i < 320) bias[i] = (i < Hn) ? attb[i] : decb[i - Hn];
}
__global__ void k_pack_misc(const float* __restrict__ attW, const float* __restrict__ decWhh,
                            float* __restrict__ attWhT, float* __restrict__ dWhhT,
                            float* __restrict__ acc) {
    int i = blockIdx.x * blockDim.x + threadIdx.x;
    if (i < 32) acc[i] = 0.0f;
    if (i < Hn * Hn) { int k = i / Hn, j = i % Hn; attWhT[i] = attW[j * 987 + k]; }
    if (i < Hn * Gn) { int k = i / Gn, j = i % Gn; dWhhT[i] = decWhh[j * Hn + k]; }
}

// ---------------- TF32 mma.sync GEMM ----------------
// C[M,N] = A[M,K](row, lda) @ Bw[N,K](row, ldb)^T + epilogue
// BM=128, BN=64, BK=16. 256 threads = 8 warps (4 m x 2 n), warp tile 32x32.
// EPI 0: +bias ; EPI 1: +add[m*addLd+n] ; EPI 2: fused histenc epilogue.
template<int EPI>
__global__ __launch_bounds__(256) void tgemm(
    const float* __restrict__ A, int lda,
    const float* __restrict__ Bw, int ldb,
    float* __restrict__ C, int ldc,
    const float* __restrict__ bias,
    const float* __restrict__ add, int addLd,
    int N, int K,
    const float* __restrict__ values, const float* __restrict__ masks,
    float* __restrict__ outImp, float* __restrict__ xcat,
    float* __restrict__ enc, float* __restrict__ accp, int t)
{
    constexpr int ST = 20;  // smem row stride (16 + 4 pad): conflict-free fragments
    __shared__ uint32_t As[2][128 * ST];
    __shared__ uint32_t Bs[2][64 * ST];
    __shared__ float rb[64];

    const int tid = threadIdx.x;
    const int lane = tid & 31, w = tid >> 5;
    const int wm = (w & 3) * 32, wn = (w >> 2) * 32;
    const int m0 = blockIdx.y * 128, n0 = blockIdx.x * 64;
    const int fr = lane >> 2, fc = lane & 3;

    // global load assignments
    const int arow = tid >> 1, aks = (tid & 1) * 8;   // A: 8 floats per thread
    const int brow = tid >> 2, bks = (tid & 3) * 4;   // B: 4 floats per thread

    float Ar[8], Br[4];
    auto loadG = [&](int k0) {
        const float* ap = A + (size_t)(m0 + arow) * lda + k0 + aks;
#pragma unroll
        for (int i = 0; i < 8; i++) Ar[i] = (k0 + aks + i < K) ? ap[i] : 0.0f;
        bool nv = (n0 + brow < N);
        const float* bp = Bw + (size_t)(n0 + brow) * ldb + k0 + bks;
#pragma unroll
        for (int i = 0; i < 4; i++) Br[i] = (nv && k0 + bks + i < K) ? bp[i] : 0.0f;
    };
    auto storeS = [&](int buf) {
#pragma unroll
        for (int i = 0; i < 8; i++) As[buf][arow * ST + aks + i] = f2tf32(Ar[i]);
#pragma unroll
        for (int i = 0; i < 4; i++) Bs[buf][brow * ST + bks + i] = f2tf32(Br[i]);
    };

    loadG(0);
    storeS(0);
    __syncthreads();

    float acc[2][4][4];
#pragma unroll
    for (int mi = 0; mi < 2; mi++)
#pragma unroll
        for (int ni = 0; ni < 4; ni++)
#pragma unroll
            for (int q = 0; q < 4; q++) acc[mi][ni][q] = 0.0f;

    const int NT = (K + 15) >> 4;
    int cur = 0;
    for (int t0 = 0; t0 < NT; t0++) {
        if (t0 + 1 < NT) loadG((t0 + 1) << 4);
#pragma unroll
        for (int k0 = 0; k0 < 16; k0 += 8) {
            uint32_t a[2][4], b[4][2];
#pragma unroll
            for (int mi = 0; mi < 2; mi++) {
                int mb = wm + mi * 16;
                a[mi][0] = As[cur][(mb + fr) * ST + k0 + fc];
                a[mi][1] = As[cur][(mb + 8 + fr) * ST + k0 + fc];
                a[mi][2] = As[cur][(mb + fr) * ST + k0 + fc + 4];
                a[mi][3] = As[cur][(mb + 8 + fr) * ST + k0 + fc + 4];
            }
#pragma unroll
            for (int ni = 0; ni < 4; ni++) {
                int nb = wn + ni * 8;
                b[ni][0] = Bs[cur][(nb + fr) * ST + k0 + fc];
                b[ni][1] = Bs[cur][(nb + fr) * ST + k0 + fc + 4];
            }
#pragma unroll
            for (int mi = 0; mi < 2; mi++)
#pragma unroll
                for (int ni = 0; ni < 4; ni++)
                    mma_tf32(acc[mi][ni], a[mi], b[ni]);
        }
        if (t0 + 1 < NT) storeS(cur ^ 1);
        __syncthreads();
        cur ^= 1;
    }

    // ---- epilogue ----
    float ds = 0.0f, ms = 0.0f;
#pragma unroll
    for (int mi = 0; mi < 2; mi++) {
#pragma unroll
        for (int ni = 0; ni < 4; ni++) {
#pragma unroll
            for (int q = 0; q < 4; q++) {
                int m = m0 + wm + mi * 16 + fr + (q >> 1) * 8;
                int n = n0 + wn + ni * 8 + fc * 2 + (q & 1);
                float v = acc[mi][ni][q];
                if (n < N) {
                    if (EPI == 0) {
                        C[(size_t)m * ldc + n] = v + bias[n];
                    } else if (EPI == 1) {
                        C[(size_t)m * ldc + n] = v + add[(size_t)m * addLd + n];
                    } else {
                        v += bias[n];
                        if (n < Fn) {
                            size_t gi = ((size_t)m * Tn + t) * Fn + n;
                            float x = values[gi], mm = masks[gi];
                            float d = (x - v) * mm;
                            ds += d * d; ms += mm;
                            float xcv = fmaf(mm, x - v, v);
                            xcat[(size_t)m * 992 + n] = xcv;
                            outImp[gi] = rnd6(xcv);
                        } else {
                            int f = n - Fn;
                            size_t gi = ((size_t)m * Tn + t) * Fn + f;
                            enc[gi] = tanhf(v) * masks[gi];
                        }
                    }
                }
            }
        }
    }
    if (EPI == 2) red2(ds, ms, rb, accp + 2 * t, accp + 2 * t + 1);
}

// ---------------- LSTM pointwise (encoder) ----------------
__global__ void k_lstm(const float* __restrict__ gates, float* __restrict__ h, float* __restrict__ c,
                       float* __restrict__ xcat, const float* __restrict__ tdPre, int t)
{
    int i = blockIdx.x * blockDim.x + threadIdx.x;
    if (i >= Bn * Hn) return;
    int b = i >> 6, j = i & 63;
    const float* g = gates + (size_t)b * Gn;
    float cv = sigmoidf_(g[64 + j]) * c[i] + sigmoidf_(g[j]) * tanhf(g[128 + j]);
    float hv = sigmoidf_(g[192 + j]) * tanhf(cv);
    c[i] = cv;
    if (t < Tn - 1) {
        float gm = expf(-fmaxf(tdPre[((size_t)b * Tn + t + 1) * Hn + j], 0.0f));
        hv *= gm;
        xcat[(size_t)b * 992 + Fn + j] = hv;
    }
    h[i] = hv;
}

__global__ void k_yh0(const float* __restrict__ pH, const float* __restrict__ outW,
                      const float* __restrict__ outb, const float* __restrict__ labels,
                      const float* __restrict__ masky, float* __restrict__ pYH,
                      float* __restrict__ outDec, float* __restrict__ accp)
{
    __shared__ float buf[64];
    int gid = blockIdx.x * blockDim.x + threadIdx.x;
    int b = gid >> 1, o = gid & 1;
    const float* hr = pH + (size_t)b * Hn;
    const float* wr = outW + o * Hn;
    float s = outb[o];
#pragma unroll
    for (int k = 0; k < Hn; k++) s += hr[k] * wr[k];
    pYH[gid] = s;
    size_t li = ((size_t)b * Tn + (Tn - 1)) * 2 + o;
    float l0 = labels[li], m0 = masky[li];
    float d = (s - l0) * m0;
    outDec[li] = rnd6(l0 * m0 + s * (1.0f - m0));
    red2(d * d, m0, buf, accp + 10, accp + 11);
}

// ---------------- fused decoder step ----------------
__global__ __launch_bounds__(256) void k_decstep(
    const float* __restrict__ labels, const float* __restrict__ masky,
    float* __restrict__ pH, float* __restrict__ pC, float* __restrict__ pYH,
    const float* __restrict__ encPG, const float* __restrict__ attWhT,
    const float* __restrict__ dWhhT, const float* __restrict__ decWih,
    const float* __restrict__ attv, const float* __restrict__ outW,
    const float* __restrict__ outb, float* __restrict__ outDec,
    float* __restrict__ accp, int td)
{
    int b = blockIdx.x, tid = threadIdx.x;
    __shared__ float sh[64], shp[64], siy[2], se[5], sattn[5], sg[256], shn[64], syh[2];
    __shared__ float rbuf[64];
    const int tr = Tn - 1 - td;

    if (tid < 64) sh[tid] = pH[(size_t)b * Hn + tid];
    if (tid >= 64 && tid < 66) {
        int o = tid - 64;
        size_t li = ((size_t)b * Tn + tr) * 2 + o;
        float lv = labels[li], mv = masky[li];
        float v = lv * mv + pYH[b * 2 + o] * (1.0f - mv);
        siy[o] = v;
        outDec[li] = rnd6(v);
    }
    __syncthreads();

    if (tid < 64) {
        float s = 0.0f;
#pragma unroll 16
        for (int k = 0; k < 64; k++) s += sh[k] * attWhT[k * 64 + tid];
        shp[tid] = s;
    }
    __syncthreads();

    int w = tid >> 5, lane = tid & 31;
    if (w < Tn) {
        const float* ep = encPG + ((size_t)b * Tn + w) * 320;
        float p = attv[lane] * tanhf(shp[lane] + ep[lane])
                + attv[lane + 32] * tanhf(shp[lane + 32] + ep[lane + 32]);
#pragma unroll
        for (int o = 16; o; o >>= 1) p += __shfl_down_sync(0xffffffffu, p, o);
        if (lane == 0) se[w] = p;
    }
    __syncthreads();
    if (tid == 0) {
        float mx = se[0];
#pragma unroll
        for (int k = 1; k < Tn; k++) mx = fmaxf(mx, se[k]);
        float sum = 0.0f;
#pragma unroll
        for (int k = 0; k < Tn; k++) { sattn[k] = expf(se[k] - mx); sum += sattn[k]; }
        float inv = 1.0f / sum;
#pragma unroll
        for (int k = 0; k < Tn; k++) sattn[k] *= inv;
    }
    __syncthreads();

    {
        const float* eg = encPG + (size_t)b * Tn * 320 + 64;
        float g = sattn[0] * eg[tid] + sattn[1] * eg[320 + tid] + sattn[2] * eg[640 + tid]
                + sattn[3] * eg[960 + tid] + sattn[4] * eg[1280 + tid];
#pragma unroll 16
        for (int k = 0; k < 64; k++) g += sh[k] * dWhhT[k * 256 + tid];
        g += siy[0] * decWih[tid * 925 + 0] + siy[1] * decWih[tid * 925 + 1];
        sg[tid] = g;
    }
    __syncthreads();

    if (tid < 64) {
        float cv = sigmoidf_(sg[64 + tid]) * pC[(size_t)b * Hn + tid]
                 + sigmoidf_(sg[tid]) * tanhf(sg[128 + tid]);
        float hv = sigmoidf_(sg[192 + tid]) * tanhf(cv);
        pC[(size_t)b * Hn + tid] = cv;
        pH[(size_t)b * Hn + tid] = hv;
        shn[tid] = hv;
    }
    __syncthreads();

    if (w < 2) {
        float p = shn[lane] * outW[w * 64 + lane] + shn[lane + 32] * outW[w * 64 + lane + 32];
#pragma unroll
        for (int o = 16; o; o >>= 1) p += __shfl_down_sync(0xffffffffu, p, o);
        if (lane == 0) { float yv = p + outb[w]; syh[w] = yv; pYH[b * 2 + w] = yv; }
    }
    __syncthreads();

    float ds = 0.0f, ms = 0.0f;
    if (tid < 2) {
        size_t li = ((size_t)b * Tn + tr) * 2 + tid;
        float d = (syh[tid] - labels[li]) * masky[li];
        ds = d * d; ms = masky[li];
    }
    red2(ds, ms, rbuf, accp + 10 + 2 * td, accp + 11 + 2 * td);
}

__global__ void k_final(const float* __restrict__ acc, float* __restrict__ out) {
    if (threadIdx.x == 0) {
        float xl = 0.0f, yl = 0.0f;
#pragma unroll
        for (int t = 0; t < Tn; t++)
            xl += (acc[2 * t] / ((float)Bn * (float)Fn)) / (acc[2 * t + 1] + EPSc);
#pragma unroll
        for (int td = 0; td < Tn; td++)
            yl += (acc[10 + 2 * td] / ((float)Bn * 2.0f)) / (acc[11 + 2 * td] + EPSc);
        out[0] = xl / (float)Tn + yl / (float)Tn;
    }
}

// ---------------- host orchestration ----------------
extern "C" void kernel_launch(void* const* d_in, const int* in_sizes, int n_in,
                              void* d_out, int out_size)
{
    const float* values  = (const float*)d_in[0];
    const float* masks   = (const float*)d_in[1];
    const float* deltas  = (const float*)d_in[2];
    const float* labels  = (const float*)d_in[3];
    const float* masks_y = (const float*)d_in[4];
    const float* td_W    = (const float*)d_in[5];
    const float* td_b    = (const float*)d_in[6];
    const float* hist_W  = (const float*)d_in[7];
    const float* hist_b  = (const float*)d_in[8];
    const float* enc_W   = (const float*)d_in[9];
    const float* enc_b   = (const float*)d_in[10];
    const float* rnn_Wih = (const float*)d_in[11];
    const float* rnn_Whh = (const float*)d_in[12];
    const float* rnn_b   = (const float*)d_in[13];
    const float* dec_Wih = (const float*)d_in[14];
    const float* dec_Whh = (const float*)d_in[15];
    const float* dec_b   = (const float*)d_in[16];
    const float* att_W   = (const float*)d_in[17];
    const float* att_b   = (const float*)d_in[18];
    const float* att_v   = (const float*)d_in[19];
    const float* out_W   = (const float*)d_in[20];
    const float* out_b   = (const float*)d_in[21];

    float* out = (float*)d_out;
    float* outImp = out + 1;
    float* outDec = out + 1 + (size_t)Bn * Tn * Fn;

    float* gb = nullptr;
    cudaGetSymbolAddress((void**)&gb, g_buf);

    float* pH     = gb + O_H;
    float* pC     = gb + O_C;
    float* pYH    = gb + O_YH;
    float* pAcc   = gb + O_ACC;
    float* pXCAT  = gb + O_XCAT;
    float* pGATES = gb + O_GATES;
    float* pENC   = gb + O_ENC;
    float* pENCPG = gb + O_ENCPG;
    float* pTDPRE = gb + O_TDPRE;
    float* pMASKG = gb + O_MASKG;
    float* pWHE2  = gb + O_WHE2;
    float* pBHE   = gb + O_BHE;
    float* pWCOMB2= gb + O_WCOMB2;
    float* pWENC2B= gb + O_WENC2B;
    float* pB2    = gb + O_B2;
    float* pATTWHT= gb + O_ATTWHT;
    float* pDWHHT = gb + O_DWHHT;

    const float* NUL = nullptr;

    // ---- launches 1-5: packs + state init ----
    k_pack_whe2  <<<(2 * Fn * Hn + 255) / 256, 256>>>(hist_W, enc_W, hist_b, enc_b, pWHE2, pBHE);
    k_pack_wcomb2<<<(Gn * 987 + 255) / 256, 256>>>(rnn_Wih, rnn_Whh, pWCOMB2);
    k_pack_wenc2b<<<(320 * Fn + 255) / 256, 256>>>(att_W, dec_Wih, att_b, dec_b, pWENC2B, pB2);
    k_pack_misc  <<<(Hn * Gn + 255) / 256, 256>>>(att_W, dec_Whh, pATTWHT, pDWHHT, pAcc);
    k_zero       <<<(2 * Bn * Hn + 255) / 256, 256>>>(pH, 2 * Bn * Hn);  // h & c

    // ---- launch #6 (ncu target): maskG = masks @ rnn_Wih[:,923:]^T + rnn_b ----
    {
        dim3 g(4, 320);
        tgemm<0><<<g, 256>>>(masks, Fn, rnn_Wih + Fn, 2 * Fn, pMASKG, Gn, rnn_b,
                             NUL, 0, Gn, Fn, NUL, NUL, nullptr, nullptr, nullptr, nullptr, 0);
    }
    // tdPre = deltas @ td_W^T + td_b  (td_W is [64,923] row-major = perfect B operand)
    {
        dim3 g(1, 320);
        tgemm<0><<<g, 256>>>(deltas, Fn, td_W, Fn, pTDPRE, Hn, td_b,
                             NUL, 0, Hn, Fn, NUL, NUL, nullptr, nullptr, nullptr, nullptr, 0);
    }

    // DETERMINISM FIX: zero xcat h-columns every call (t=0 gates GEMM reads them as h=0;
    // k_lstm overwrites them only for t<4, so stale state leaked across graph replays).
    k_zerocols<<<(Bn * 69 + 255) / 256, 256>>>(pXCAT);

    // ---- encoder ----
    for (int t = 0; t < Tn; t++) {
        // hist+enc fused: [8192,1846] = h[8192,64] @ WHE2^T ; K=64
        {
            dim3 g((2 * Fn + 63) / 64, Bn / 128);
            tgemm<2><<<g, 256>>>(pH, Hn, pWHE2, Hn, nullptr, 0, pBHE,
                                 NUL, 0, 2 * Fn, Hn,
                                 values, masks, outImp, pXCAT, pENC, pAcc, t);
        }
        // gates: [8192,256] = xcat[8192,992(K=987)] @ WCOMB2^T + maskG[:,t,:]
        {
            dim3 g(4, Bn / 128);
            tgemm<1><<<g, 256>>>(pXCAT, 992, pWCOMB2, 987, pGATES, Gn, NUL,
                                 pMASKG + (size_t)t * Gn, Tn * Gn, Gn, 987,
                                 NUL, NUL, nullptr, nullptr, nullptr, nullptr, 0);
        }
        k_lstm<<<(Bn * Hn + 255) / 256, 256>>>(pGATES, pH, pC, pXCAT, pTDPRE, t);
    }

    // ---- y_h + first decoder output ----
    k_yh0<<<Bn * 2 / 128, 128>>>(pH, out_W, out_b, labels, masks_y, pYH, outDec, pAcc);

    // encPG = enc @ WENC2B^T + B2 ; [40960,320] K=923
    {
        dim3 g(5, 320);
        tgemm<0><<<g, 256>>>(pENC, Fn, pWENC2B, Fn, pENCPG, 320, pB2,
                             NUL, 0, 320, Fn, NUL, NUL, nullptr, nullptr, nullptr, nullptr, 0);
    }

    // ---- decoder ----
    for (int td = 1; td < Tn; td++) {
        k_decstep<<<Bn, 256>>>(labels, masks_y, pH, pC, pYH, pENCPG, pATTWHT,
                               pDWHHT, dec_Wih, att_v, out_W, out_b, outDec, pAcc, td);
    }

    k_final<<<1, 32>>>(pAcc, out);
}

// round 8
// speedup vs baseline: 2.2219x; 1.3497x over previous
#include <cuda_runtime.h>
#include <math.h>
#include <stdint.h>

#define Bn 8192
#define Tn 5
#define Fn 923
#define FnP 928
#define XST 992
#define Hn 64
#define Gn 256
#define EPSc 1e-5f

// ---------------- scratch layout ----------------
constexpr size_t AL(size_t x) { return (x + 15) & ~(size_t)15; }

constexpr size_t O_H      = 0;
constexpr size_t O_C      = AL(O_H + (size_t)Bn * Hn);
constexpr size_t O_HTF    = AL(O_C + (size_t)Bn * Hn);            // tf32-rounded h (GEMM A)
constexpr size_t O_YH     = AL(O_HTF + (size_t)Bn * Hn);
constexpr size_t O_ACC    = AL(O_YH + (size_t)Bn * 2);
constexpr size_t O_XCAT   = AL(O_ACC + 32);                       // [B, 992]
constexpr size_t O_GATES  = AL(O_XCAT + (size_t)Bn * XST);        // [B, 256]
constexpr size_t O_ENC    = AL(O_GATES + (size_t)Bn * Gn);        // [B*T, 928]
constexpr size_t O_ENCPG  = AL(O_ENC + (size_t)Bn * Tn * FnP);    // [B,T,320]
constexpr size_t O_TDPRE  = AL(O_ENCPG + (size_t)Bn * Tn * 320);  // [B,T,64]
constexpr size_t O_MASKG  = AL(O_TDPRE + (size_t)Bn * Tn * Hn);   // [B,T,256]
constexpr size_t O_WHE2   = AL(O_MASKG + (size_t)Bn * Tn * Gn);   // [1846,64]
constexpr size_t O_BHE    = AL(O_WHE2 + (size_t)2 * Fn * Hn);     // [1846]
constexpr size_t O_WCOMB2 = AL(O_BHE + 2 * Fn);                   // [256,992]
constexpr size_t O_WENC2B = AL(O_WCOMB2 + (size_t)Gn * XST);      // [320,928]
constexpr size_t O_B2     = AL(O_WENC2B + (size_t)320 * FnP);     // [320]
constexpr size_t O_ATTWHT = AL(O_B2 + 320);                       // [64,64]
constexpr size_t O_DWHHT  = AL(O_ATTWHT + Hn * Hn);               // [64,256]
constexpr size_t O_MASKWP = AL(O_DWHHT + (size_t)Hn * Gn);        // [256,928]
constexpr size_t O_TDWP   = AL(O_MASKWP + (size_t)Gn * FnP);      // [64,928]
constexpr size_t TOTAL_FLOATS = AL(O_TDWP + (size_t)Hn * FnP) + 16;

static __device__ __align__(256) float g_buf[TOTAL_FLOATS];

// ---------------- helpers ----------------
__device__ __forceinline__ float sigmoidf_(float x) { return 1.0f / (1.0f + expf(-x)); }
__device__ __forceinline__ float rnd6(float v) { return rintf(v * 1e6f) / 1e6f; }
__device__ __forceinline__ uint32_t f2tf32(float v) {
    uint32_t r; asm("cvt.rna.tf32.f32 %0, %1;" : "=r"(r) : "f"(v)); return r;
}
__device__ __forceinline__ float tf32f(float v) { return __uint_as_float(f2tf32(v)); }
__device__ __forceinline__ uint32_t smem_u32(const void* p) {
    uint32_t a;
    asm("{ .reg .u64 t; cvta.to.shared.u64 t, %1; cvt.u32.u64 %0, t; }" : "=r"(a) : "l"(p));
    return a;
}
__device__ __forceinline__ void cp16(uint32_t dst, const void* src, int bytes) {
    asm volatile("cp.async.ca.shared.global [%0], [%1], 16, %2;"
                 :: "r"(dst), "l"(src), "r"(bytes));
}
__device__ __forceinline__ void cp4(uint32_t dst, const void* src, int bytes) {
    asm volatile("cp.async.ca.shared.global [%0], [%1], 4, %2;"
                 :: "r"(dst), "l"(src), "r"(bytes));
}
#define CP_COMMIT() asm volatile("cp.async.commit_group;" ::: "memory")
#define CP_WAIT1()  asm volatile("cp.async.wait_group 1;" ::: "memory")

__device__ __forceinline__ void mma_tf32(float* d, const uint32_t* a, const uint32_t* b) {
    asm volatile(
        "mma.sync.aligned.m16n8k8.row.col.f32.tf32.tf32.f32 "
        "{%0,%1,%2,%3}, {%4,%5,%6,%7}, {%8,%9}, {%0,%1,%2,%3};"
        : "+f"(d[0]), "+f"(d[1]), "+f"(d[2]), "+f"(d[3])
        : "r"(a[0]), "r"(a[1]), "r"(a[2]), "r"(a[3]), "r"(b[0]), "r"(b[1]));
}

__device__ __forceinline__ void red2(float v0, float v1, float* buf, float* a0, float* a1) {
    int lane = threadIdx.x & 31, w = threadIdx.x >> 5;
#pragma unroll
    for (int o = 16; o; o >>= 1) {
        v0 += __shfl_down_sync(0xffffffffu, v0, o);
        v1 += __shfl_down_sync(0xffffffffu, v1, o);
    }
    if (lane == 0) { buf[w] = v0; buf[32 + w] = v1; }
    __syncthreads();
    if (w == 0) {
        int nw = (blockDim.x + 31) >> 5;
        v0 = (lane < nw) ? buf[lane] : 0.0f;
        v1 = (lane < nw) ? buf[32 + lane] : 0.0f;
#pragma unroll
        for (int o = 16; o; o >>= 1) {
            v0 += __shfl_down_sync(0xffffffffu, v0, o);
            v1 += __shfl_down_sync(0xffffffffu, v1, o);
        }
        if (lane == 0) { atomicAdd(a0, v0); atomicAdd(a1, v1); }
    }
}

// ---------------- pack / init kernels ----------------
__global__ void k_zero(float* p, int n) {
    int i = blockIdx.x * blockDim.x + threadIdx.x;
    if (i < n) p[i] = 0.0f;
}
__global__ void k_zerocols(float* xcat) {
    int i = blockIdx.x * blockDim.x + threadIdx.x;
    if (i < Bn * 69) { int b = i / 69, j = i % 69; xcat[(size_t)b * XST + 923 + j] = 0.0f; }
}
// WHE2 [1846,64] (rna-rounded), bias [1846]
__global__ void k_pack_whe2(const float* __restrict__ histW, const float* __restrict__ encW,
                            const float* __restrict__ histb, const float* __restrict__ encb,
                            float* __restrict__ dst, float* __restrict__ bias) {
    int i = blockIdx.x * blockDim.x + threadIdx.x;
    if (i < 2 * Fn * Hn) dst[i] = tf32f((i < Fn * Hn) ? histW[i] : encW[i - Fn * Hn]);
    if (i < 2 * Fn) bias[i] = (i < Fn) ? histb[i] : encb[i - Fn];
}
// WCOMB2 [256, 992] stride-padded, rna
__global__ void k_pack_wcomb2(const float* __restrict__ Wih, const float* __restrict__ Whh,
                              float* __restrict__ dst) {
    int i = blockIdx.x * blockDim.x + threadIdx.x;
    if (i < Gn * XST) {
        int n = i / XST, k = i % XST;
        float v = 0.0f;
        if (k < Fn) v = Wih[(size_t)n * (2 * Fn) + k];
        else if (k < 987) v = Whh[n * Hn + (k - Fn)];
        dst[i] = tf32f(v);
    }
}
// WENC2B [320, 928] stride-padded, rna
__global__ void k_pack_wenc2b(const float* __restrict__ attW, const float* __restrict__ decWih,
                              const float* __restrict__ attb, const float* __restrict__ decb,
                              float* __restrict__ dst, float* __restrict__ bias) {
    int i = blockIdx.x * blockDim.x + threadIdx.x;
    if (i < 320 * FnP) {
        int n = i / FnP, k = i % FnP;
        float v = 0.0f;
        if (k < Fn) v = (n < Hn) ? attW[n * 987 + Hn + k] : decWih[(size_t)(n - Hn) * 925 + 2 + k];
        dst[i] = tf32f(v);
    }
    if (i < 320) bias[i] = (i < Hn) ? attb[i] : decb[i - Hn];
}
// small packs: maskWP [256,928], tdWP [64,928] (rna), attWhT, dWhhT (fp32), acc zero
__global__ void k_pack_small(const float* __restrict__ Wih, const float* __restrict__ tdW,
                             const float* __restrict__ attW, const float* __restrict__ decWhh,
                             float* __restrict__ maskWP, float* __restrict__ tdWP,
                             float* __restrict__ attWhT, float* __restrict__ dWhhT,
                             float* __restrict__ acc) {
    int i = blockIdx.x * blockDim.x + threadIdx.x;
    if (i < Gn * FnP) {
        int n = i / FnP, k = i % FnP;
        maskWP[i] = tf32f((k < Fn) ? Wih[(size_t)n * (2 * Fn) + Fn + k] : 0.0f);
    }
    if (i < Hn * FnP) {
        int n = i / FnP, k = i % FnP;
        tdWP[i] = tf32f((k < Fn) ? tdW[n * Fn + k] : 0.0f);
    }
    if (i < Hn * Hn) { int k = i / Hn, j = i % Hn; attWhT[i] = attW[j * 987 + k]; }
    if (i < Hn * Gn) { int k = i / Gn, j = i % Gn; dWhhT[i] = decWhh[j * Hn + k]; }
    if (i < 32) acc[i] = 0.0f;
}

// ---------------- TF32 mma.sync GEMM, cp.async 3-stage pipeline ----------------
// C[M,N] = A[M,K](row, lda) @ Bw[N,K](row, ldb)^T + epilogue
// BM=128, BN=64, BK=16. 256 threads = 8 warps (4m x 2n), warp tile 32x32.
// A16: A rows are 16B aligned (use cp16) else 4B path. B must be 16B aligned.
// EPI 0: +bias ; EPI 1: +add[m*addLd+n] ; EPI 2: fused histenc epilogue.
template<int EPI, int A16>
__global__ __launch_bounds__(256) void tgemm(
    const float* __restrict__ A, int lda,
    const float* __restrict__ Bw, int ldb,
    float* __restrict__ C, int ldc,
    const float* __restrict__ bias,
    const float* __restrict__ add, int addLd,
    int N, int K,
    const float* __restrict__ values, const float* __restrict__ masks,
    float* __restrict__ outImp, float* __restrict__ xcat,
    float* __restrict__ enc, float* __restrict__ accp, int t)
{
    constexpr int ST = 20;       // smem row stride (16+4 pad): conflict-free fragments
    constexpr int STG = 3;
    __shared__ __align__(16) uint32_t As[STG][128 * ST];
    __shared__ __align__(16) uint32_t Bs[STG][64 * ST];
    __shared__ float rb[64];

    const int tid = threadIdx.x;
    const int lane = tid & 31, w = tid >> 5;
    const int wm = (w & 3) * 32, wn = (w >> 2) * 32;
    const int m0 = blockIdx.y * 128, n0 = blockIdx.x * 64;
    const int fr = lane >> 2, fc = lane & 3;

    const int arow = tid >> 1, aks = (tid & 1) * 8;   // A: 8 floats per thread
    const int brow = tid >> 2, bks = (tid & 3) * 4;   // B: 4 floats per thread

    const uint32_t aSm = smem_u32(&As[0][0]);
    const uint32_t bSm = smem_u32(&Bs[0][0]);
    const bool bOk = (n0 + brow < N);
    const int bRow = bOk ? (n0 + brow) : (N - 1);     // clamp: no OOB address formation
    const float* aPtr = A + (size_t)(m0 + arow) * lda + aks;
    const float* bPtr = Bw + (size_t)bRow * ldb + bks;

    auto clampB = [&](int k) -> int {
        int r = (K - k) * 4;
        return r < 0 ? 0 : (r > 16 ? 16 : r);
    };
    auto issue = [&](int kt, int s) {
        int k0 = kt << 4;
        uint32_t da = aSm + (uint32_t)(s * 128 * ST + arow * ST + aks) * 4;
        if (A16) {
            cp16(da,      aPtr + k0,     clampB(k0 + aks));
            cp16(da + 16, aPtr + k0 + 4, clampB(k0 + aks + 4));
        } else {
#pragma unroll
            for (int i = 0; i < 8; i++)
                cp4(da + 4 * i, aPtr + k0 + i, (k0 + aks + i < K) ? 4 : 0);
        }
        uint32_t db = bSm + (uint32_t)(s * 64 * ST + brow * ST + bks) * 4;
        cp16(db, bPtr + k0, bOk ? clampB(k0 + bks) : 0);
    };

    const int NT = (K + 15) >> 4;
#pragma unroll
    for (int s = 0; s < STG - 1; s++) {
        if (s < NT) issue(s, s);
        CP_COMMIT();
    }

    float acc[2][4][4];
#pragma unroll
    for (int mi = 0; mi < 2; mi++)
#pragma unroll
        for (int ni = 0; ni < 4; ni++)
#pragma unroll
            for (int q = 0; q < 4; q++) acc[mi][ni][q] = 0.0f;

    for (int t0 = 0; t0 < NT; t0++) {
        CP_WAIT1();
        __syncthreads();
        int pre = t0 + STG - 1;
        if (pre < NT) issue(pre, pre % STG);
        CP_COMMIT();

        const uint32_t* as = As[t0 % STG];
        const uint32_t* bs = Bs[t0 % STG];
#pragma unroll
        for (int k0 = 0; k0 < 16; k0 += 8) {
            uint32_t a[2][4], b[4][2];
#pragma unroll
            for (int mi = 0; mi < 2; mi++) {
                int mb = wm + mi * 16;
                a[mi][0] = as[(mb + fr) * ST + k0 + fc];
                a[mi][1] = as[(mb + 8 + fr) * ST + k0 + fc];
                a[mi][2] = as[(mb + fr) * ST + k0 + fc + 4];
                a[mi][3] = as[(mb + 8 + fr) * ST + k0 + fc + 4];
            }
#pragma unroll
            for (int ni = 0; ni < 4; ni++) {
                int nb = wn + ni * 8;
                b[ni][0] = bs[(nb + fr) * ST + k0 + fc];
                b[ni][1] = bs[(nb + fr) * ST + k0 + fc + 4];
            }
#pragma unroll
            for (int mi = 0; mi < 2; mi++)
#pragma unroll
                for (int ni = 0; ni < 4; ni++)
                    mma_tf32(acc[mi][ni], a[mi], b[ni]);
        }
    }

    // ---- epilogue ----
    float ds = 0.0f, ms = 0.0f;
#pragma unroll
    for (int mi = 0; mi < 2; mi++) {
#pragma unroll
        for (int ni = 0; ni < 4; ni++) {
#pragma unroll
            for (int q = 0; q < 4; q++) {
                int m = m0 + wm + mi * 16 + fr + (q >> 1) * 8;
                int n = n0 + wn + ni * 8 + fc * 2 + (q & 1);
                float v = acc[mi][ni][q];
                if (n < N) {
                    if (EPI == 0) {
                        C[(size_t)m * ldc + n] = v + bias[n];
                    } else if (EPI == 1) {
                        C[(size_t)m * ldc + n] = v + add[(size_t)m * addLd + n];
                    } else {
                        v += bias[n];
                        if (n < Fn) {
                            size_t gi = ((size_t)m * Tn + t) * Fn + n;
                            float x = values[gi], mm = masks[gi];
                            float d = (x - v) * mm;
                            ds += d * d; ms += mm;
                            float xcv = fmaf(mm, x - v, v);
                            xcat[(size_t)m * XST + n] = tf32f(xcv);
                            outImp[gi] = rnd6(xcv);
                        } else {
                            int f = n - Fn;
                            size_t gi = ((size_t)m * Tn + t) * Fn + f;
                            enc[((size_t)m * Tn + t) * FnP + f] = tf32f(tanhf(v) * masks[gi]);
                        }
                    }
                }
            }
        }
    }
    if (EPI == 2) { __syncthreads(); red2(ds, ms, rb, accp + 2 * t, accp + 2 * t + 1); }
}

// ---------------- LSTM pointwise (encoder) ----------------
__global__ void k_lstm(const float* __restrict__ gates, float* __restrict__ h, float* __restrict__ c,
                       float* __restrict__ htf, float* __restrict__ xcat,
                       const float* __restrict__ tdPre, int t)
{
    int i = blockIdx.x * blockDim.x + threadIdx.x;
    if (i >= Bn * Hn) return;
    int b = i >> 6, j = i & 63;
    const float* g = gates + (size_t)b * Gn;
    float cv = sigmoidf_(g[64 + j]) * c[i] + sigmoidf_(g[j]) * tanhf(g[128 + j]);
    float hv = sigmoidf_(g[192 + j]) * tanhf(cv);
    c[i] = cv;
    if (t < Tn - 1) {
        float gm = expf(-fmaxf(tdPre[((size_t)b * Tn + t + 1) * Hn + j], 0.0f));
        hv *= gm;
        xcat[(size_t)b * XST + Fn + j] = tf32f(hv);
    }
    h[i] = hv;
    htf[i] = tf32f(hv);
}

__global__ void k_yh0(const float* __restrict__ pH, const float* __restrict__ outW,
                      const float* __restrict__ outb, const float* __restrict__ labels,
                      const float* __restrict__ masky, float* __restrict__ pYH,
                      float* __restrict__ outDec, float* __restrict__ accp)
{
    __shared__ float buf[64];
    int gid = blockIdx.x * blockDim.x + threadIdx.x;
    int b = gid >> 1, o = gid & 1;
    const float* hr = pH + (size_t)b * Hn;
    const float* wr = outW + o * Hn;
    float s = outb[o];
#pragma unroll
    for (int k = 0; k < Hn; k++) s += hr[k] * wr[k];
    pYH[gid] = s;
    size_t li = ((size_t)b * Tn + (Tn - 1)) * 2 + o;
    float l0 = labels[li], m0 = masky[li];
    float d = (s - l0) * m0;
    outDec[li] = rnd6(l0 * m0 + s * (1.0f - m0));
    red2(d * d, m0, buf, accp + 10, accp + 11);
}

// ---------------- fused decoder step ----------------
__global__ __launch_bounds__(256) void k_decstep(
    const float* __restrict__ labels, const float* __restrict__ masky,
    float* __restrict__ pH, float* __restrict__ pC, float* __restrict__ pYH,
    const float* __restrict__ encPG, const float* __restrict__ attWhT,
    const float* __restrict__ dWhhT, const float* __restrict__ decWih,
    const float* __restrict__ attv, const float* __restrict__ outW,
    const float* __restrict__ outb, float* __restrict__ outDec,
    float* __restrict__ accp, int td)
{
    int b = blockIdx.x, tid = threadIdx.x;
    __shared__ float sh[64], shp[64], siy[2], se[5], sattn[5], sg[256], shn[64], syh[2];
    __shared__ float rbuf[64];
    const int tr = Tn - 1 - td;

    if (tid < 64) sh[tid] = pH[(size_t)b * Hn + tid];
    if (tid >= 64 && tid < 66) {
        int o = tid - 64;
        size_t li = ((size_t)b * Tn + tr) * 2 + o;
        float lv = labels[li], mv = masky[li];
        float v = lv * mv + pYH[b * 2 + o] * (1.0f - mv);
        siy[o] = v;
        outDec[li] = rnd6(v);
    }
    __syncthreads();

    if (tid < 64) {
        float s = 0.0f;
#pragma unroll 16
        for (int k = 0; k < 64; k++) s += sh[k] * attWhT[k * 64 + tid];
        shp[tid] = s;
    }
    __syncthreads();

    int w = tid >> 5, lane = tid & 31;
    if (w < Tn) {
        const float* ep = encPG + ((size_t)b * Tn + w) * 320;
        float p = attv[lane] * tanhf(shp[lane] + ep[lane])
                + attv[lane + 32] * tanhf(shp[lane + 32] + ep[lane + 32]);
#pragma unroll
        for (int o = 16; o; o >>= 1) p += __shfl_down_sync(0xffffffffu, p, o);
        if (lane == 0) se[w] = p;
    }
    __syncthreads();
    if (tid == 0) {
        float mx = se[0];
#pragma unroll
        for (int k = 1; k < Tn; k++) mx = fmaxf(mx, se[k]);
        float sum = 0.0f;
#pragma unroll
        for (int k = 0; k < Tn; k++) { sattn[k] = expf(se[k] - mx); sum += sattn[k]; }
        float inv = 1.0f / sum;
#pragma unroll
        for (int k = 0; k < Tn; k++) sattn[k] *= inv;
    }
    __syncthreads();

    {
        const float* eg = encPG + (size_t)b * Tn * 320 + 64;
        float g = sattn[0] * eg[tid] + sattn[1] * eg[320 + tid] + sattn[2] * eg[640 + tid]
                + sattn[3] * eg[960 + tid] + sattn[4] * eg[1280 + tid];
#pragma unroll 16
        for (int k = 0; k < 64; k++) g += sh[k] * dWhhT[k * 256 + tid];
        g += siy[0] * decWih[tid * 925 + 0] + siy[1] * decWih[tid * 925 + 1];
        sg[tid] = g;
    }
    __syncthreads();

    if (tid < 64) {
        float cv = sigmoidf_(sg[64 + tid]) * pC[(size_t)b * Hn + tid]
                 + sigmoidf_(sg[tid]) * tanhf(sg[128 + tid]);
        float hv = sigmoidf_(sg[192 + tid]) * tanhf(cv);
        pC[(size_t)b * Hn + tid] = cv;
        pH[(size_t)b * Hn + tid] = hv;
        shn[tid] = hv;
    }
    __syncthreads();

    if (w < 2) {
        float p = shn[lane] * outW[w * 64 + lane] + shn[lane + 32] * outW[w * 64 + lane + 32];
#pragma unroll
        for (int o = 16; o; o >>= 1) p += __shfl_down_sync(0xffffffffu, p, o);
        if (lane == 0) { float yv = p + outb[w]; syh[w] = yv; pYH[b * 2 + w] = yv; }
    }
    __syncthreads();

    float ds = 0.0f, ms = 0.0f;
    if (tid < 2) {
        size_t li = ((size_t)b * Tn + tr) * 2 + tid;
        float d = (syh[tid] - labels[li]) * masky[li];
        ds = d * d; ms = masky[li];
    }
    red2(ds, ms, rbuf, accp + 10 + 2 * td, accp + 11 + 2 * td);
}

__global__ void k_final(const float* __restrict__ acc, float* __restrict__ out) {
    if (threadIdx.x == 0) {
        float xl = 0.0f, yl = 0.0f;
#pragma unroll
        for (int t = 0; t < Tn; t++)
            xl += (acc[2 * t] / ((float)Bn * (float)Fn)) / (acc[2 * t + 1] + EPSc);
#pragma unroll
        for (int td = 0; td < Tn; td++)
            yl += (acc[10 + 2 * td] / ((float)Bn * 2.0f)) / (acc[11 + 2 * td] + EPSc);
        out[0] = xl / (float)Tn + yl / (float)Tn;
    }
}

// ---------------- host orchestration ----------------
extern "C" void kernel_launch(void* const* d_in, const int* in_sizes, int n_in,
                              void* d_out, int out_size)
{
    const float* values  = (const float*)d_in[0];
    const float* masks   = (const float*)d_in[1];
    const float* deltas  = (const float*)d_in[2];
    const float* labels  = (const float*)d_in[3];
    const float* masks_y = (const float*)d_in[4];
    const float* td_W    = (const float*)d_in[5];
    const float* td_b    = (const float*)d_in[6];
    const float* hist_W  = (const float*)d_in[7];
    const float* hist_b  = (const float*)d_in[8];
    const float* enc_W   = (const float*)d_in[9];
    const float* enc_b   = (const float*)d_in[10];
    const float* rnn_Wih = (const float*)d_in[11];
    const float* rnn_Whh = (const float*)d_in[12];
    const float* rnn_b   = (const float*)d_in[13];
    const float* dec_Wih = (const float*)d_in[14];
    const float* dec_Whh = (const float*)d_in[15];
    const float* dec_b   = (const float*)d_in[16];
    const float* att_W   = (const float*)d_in[17];
    const float* att_b   = (const float*)d_in[18];
    const float* att_v   = (const float*)d_in[19];
    const float* out_W   = (const float*)d_in[20];
    const float* out_b   = (const float*)d_in[21];

    float* out = (float*)d_out;
    float* outImp = out + 1;
    float* outDec = out + 1 + (size_t)Bn * Tn * Fn;

    float* gb = nullptr;
    cudaGetSymbolAddress((void**)&gb, g_buf);

    float* pH     = gb + O_H;
    float* pC     = gb + O_C;
    float* pHTF   = gb + O_HTF;
    float* pYH    = gb + O_YH;
    float* pAcc   = gb + O_ACC;
    float* pXCAT  = gb + O_XCAT;
    float* pGATES = gb + O_GATES;
    float* pENC   = gb + O_ENC;
    float* pENCPG = gb + O_ENCPG;
    float* pTDPRE = gb + O_TDPRE;
    float* pMASKG = gb + O_MASKG;
    float* pWHE2  = gb + O_WHE2;
    float* pBHE   = gb + O_BHE;
    float* pWCOMB2= gb + O_WCOMB2;
    float* pWENC2B= gb + O_WENC2B;
    float* pB2    = gb + O_B2;
    float* pATTWHT= gb + O_ATTWHT;
    float* pDWHHT = gb + O_DWHHT;
    float* pMASKWP= gb + O_MASKWP;
    float* pTDWP  = gb + O_TDWP;

    const float* NUL = nullptr;

    // ---- launches 1-3: packs ----
    k_pack_whe2  <<<(2 * Fn * Hn + 255) / 256, 256>>>(hist_W, enc_W, hist_b, enc_b, pWHE2, pBHE);
    k_pack_wcomb2<<<(Gn * XST + 255) / 256, 256>>>(rnn_Wih, rnn_Whh, pWCOMB2);
    k_pack_small <<<(Gn * FnP + 255) / 256, 256>>>(rnn_Wih, td_W, att_W, dec_Whh,
                                                   pMASKWP, pTDWP, pATTWHT, pDWHHT, pAcc);

    // ---- launch #4 (ncu target): maskG = masks @ maskWP^T + rnn_b ----
    {
        dim3 g(4, 320);
        tgemm<0, 0><<<g, 256>>>(masks, Fn, pMASKWP, FnP, pMASKG, Gn, rnn_b,
                                NUL, 0, Gn, Fn, NUL, NUL, nullptr, nullptr, nullptr, nullptr, 0);
    }

    k_pack_wenc2b<<<(320 * FnP + 255) / 256, 256>>>(att_W, dec_Wih, att_b, dec_b, pWENC2B, pB2);
    k_zero       <<<(3 * Bn * Hn + 255) / 256, 256>>>(pH, 3 * Bn * Hn);  // h, c, htf
    k_zerocols   <<<(Bn * 69 + 255) / 256, 256>>>(pXCAT);                // determinism

    // tdPre = deltas @ tdWP^T + td_b
    {
        dim3 g(1, 320);
        tgemm<0, 0><<<g, 256>>>(deltas, Fn, pTDWP, FnP, pTDPRE, Hn, td_b,
                                NUL, 0, Hn, Fn, NUL, NUL, nullptr, nullptr, nullptr, nullptr, 0);
    }

    // ---- encoder ----
    for (int t = 0; t < Tn; t++) {
        {   // hist+enc fused: [8192,1846] = htf[8192,64] @ WHE2^T ; K=64
            dim3 g((2 * Fn + 63) / 64, Bn / 128);
            tgemm<2, 1><<<g, 256>>>(pHTF, Hn, pWHE2, Hn, nullptr, 0, pBHE,
                                    NUL, 0, 2 * Fn, Hn,
                                    values, masks, outImp, pXCAT, pENC, pAcc, t);
        }
        {   // gates: [8192,256] = xcat[8192, 992(K=987)] @ WCOMB2^T + maskG[:,t,:]
            dim3 g(4, Bn / 128);
            tgemm<1, 1><<<g, 256>>>(pXCAT, XST, pWCOMB2, XST, pGATES, Gn, NUL,
                                    pMASKG + (size_t)t * Gn, Tn * Gn, Gn, 987,
                                    NUL, NUL, nullptr, nullptr, nullptr, nullptr, 0);
        }
        k_lstm<<<(Bn * Hn + 255) / 256, 256>>>(pGATES, pH, pC, pHTF, pXCAT, pTDPRE, t);
    }

    // ---- y_h + first decoder output ----
    k_yh0<<<Bn * 2 / 128, 128>>>(pH, out_W, out_b, labels, masks_y, pYH, outDec, pAcc);

    // encPG = enc @ WENC2B^T + B2 ; [40960,320] K=923
    {
        dim3 g(5, 320);
        tgemm<0, 1><<<g, 256>>>(pENC, FnP, pWENC2B, FnP, pENCPG, 320, pB2,
                                NUL, 0, 320, Fn, NUL, NUL, nullptr, nullptr, nullptr, nullptr, 0);
    }

    // ---- decoder ----
    for (int td = 1; td < Tn; td++) {
        k_decstep<<<Bn, 256>>>(labels, masks_y, pH, pC, pYH, pENCPG, pATTWHT,
                               pDWHHT, dec_Wih, att_v, out_W, out_b, outDec, pAcc, td);
    }

    k_final<<<1, 32>>>(pAcc, out);
}